// round 1
// baseline (speedup 1.0000x reference)
#include <cuda_runtime.h>
#include <cstdint>

// Embedding gather: out[i, :] = weight[indices[i], :]
// indices: 819200 int32, weight: 1,000,000 x 64 fp32, out: 819200 x 64 fp32.
// Each row is 64 floats = 16 float4. 16 consecutive threads handle one row,
// so each row's 256B (2 x 128B lines) is fully coalesced on both read and write.

static constexpr int EMBED_DIM   = 64;
static constexpr int VEC_PER_ROW = EMBED_DIM / 4;  // 16 float4 per row

__global__ __launch_bounds__(256)
void embed_gather_kernel(const int* __restrict__ indices,
                         const float4* __restrict__ weight,
                         float4* __restrict__ out,
                         int num_rows)
{
    int tid = blockIdx.x * blockDim.x + threadIdx.x;
    int row = tid >> 4;          // / VEC_PER_ROW
    int seg = tid & 15;          // % VEC_PER_ROW
    if (row >= num_rows) return;

    int idx = __ldg(indices + row);
    // gather one float4 of the selected table row
    float4 v = __ldg(weight + (long long)idx * VEC_PER_ROW + seg);
    out[(long long)row * VEC_PER_ROW + seg] = v;
}

extern "C" void kernel_launch(void* const* d_in, const int* in_sizes, int n_in,
                              void* d_out, int out_size)
{
    const int*    indices = (const int*)d_in[0];     // 16384*50 = 819200 int32
    const float4* weight  = (const float4*)d_in[1];  // 1e6 x 64 fp32
    float4*       out     = (float4*)d_out;

    int num_rows = in_sizes[0];                      // 819200
    long long total_vec = (long long)num_rows * VEC_PER_ROW;

    int threads = 256;
    int blocks  = (int)((total_vec + threads - 1) / threads);
    embed_gather_kernel<<<blocks, threads>>>(indices, weight, out, num_rows);
}

// round 2
// speedup vs baseline: 1.1930x; 1.1930x over previous
#include <cuda_runtime.h>
#include <cstdint>

// Embedding gather: out[i, :] = weight[indices[i], :]
// 819200 rows of 64 fp32 (16 float4 each). 16 consecutive threads per row ->
// both the 256B gather read and the write are fully line-coalesced.
//
// v2: unroll 4 items/thread with front-batched independent loads (MLP=4+),
// streaming stores so the output doesn't evict table rows from L2.

static constexpr int VEC_PER_ROW = 16;   // 64 fp32 = 16 float4
static constexpr int UNROLL      = 4;

__global__ __launch_bounds__(256)
void embed_gather_kernel(const int* __restrict__ indices,
                         const float4* __restrict__ weight,
                         float4* __restrict__ out,
                         long long total_vec)
{
    long long stride = (long long)gridDim.x * blockDim.x;
    long long base   = (long long)blockIdx.x * blockDim.x + threadIdx.x;

    long long pos[UNROLL];
    bool      ok[UNROLL];
#pragma unroll
    for (int k = 0; k < UNROLL; k++) {
        pos[k] = base + (long long)k * stride;
        ok[k]  = pos[k] < total_vec;
    }

    // Batch 1: all index loads (independent)
    int idx[UNROLL];
#pragma unroll
    for (int k = 0; k < UNROLL; k++)
        idx[k] = ok[k] ? __ldg(indices + (pos[k] >> 4)) : 0;

    // Batch 2: all gather loads (independent, MLP=4 x 128b)
    float4 v[UNROLL];
#pragma unroll
    for (int k = 0; k < UNROLL; k++)
        if (ok[k])
            v[k] = __ldg(weight + (long long)idx[k] * VEC_PER_ROW + (pos[k] & 15));

    // Batch 3: streaming stores (output is never re-read; keep L2 for the table)
#pragma unroll
    for (int k = 0; k < UNROLL; k++)
        if (ok[k])
            __stcs(out + pos[k], v[k]);
}

extern "C" void kernel_launch(void* const* d_in, const int* in_sizes, int n_in,
                              void* d_out, int out_size)
{
    const int*    indices = (const int*)d_in[0];     // 819200 int32
    const float4* weight  = (const float4*)d_in[1];  // 1e6 x 64 fp32
    float4*       out     = (float4*)d_out;

    long long num_rows  = in_sizes[0];
    long long total_vec = num_rows * VEC_PER_ROW;    // 13,107,200

    int threads = 256;
    long long per_block = (long long)threads * UNROLL;
    int blocks = (int)((total_vec + per_block - 1) / per_block);   // 12800
    embed_gather_kernel<<<blocks, threads>>>(indices, weight, out, total_vec);
}

// round 4
// speedup vs baseline: 1.2225x; 1.0247x over previous
#include <cuda_runtime.h>
#include <cstdint>

// Embedding gather: out[i, :] = weight[indices[i], :]
// 819200 rows x 64 fp32 = 256B/row. v4: 256-bit gathers (8 threads/row) with
// L2::evict_last (keep repeated table rows in L2; ~32% of draws are repeats),
// streaming 128-bit stores, UNROLL=4, zero predication on the exact path.

static constexpr int UNROLL = 4;

struct V8 { uint32_t r[8]; };

__device__ __forceinline__ V8 ldg256_evict_last(const uint32_t* p) {
    V8 v;
    asm volatile("ld.global.nc.L2::evict_last.v8.b32 {%0,%1,%2,%3,%4,%5,%6,%7}, [%8];"
                 : "=r"(v.r[0]), "=r"(v.r[1]), "=r"(v.r[2]), "=r"(v.r[3]),
                   "=r"(v.r[4]), "=r"(v.r[5]), "=r"(v.r[6]), "=r"(v.r[7])
                 : "l"(p));
    return v;
}

__device__ __forceinline__ void stcs128(float4* p, const uint32_t* r) {
    asm volatile("st.global.cs.v4.b32 [%0], {%1,%2,%3,%4};"
                 :: "l"(p), "r"(r[0]), "r"(r[1]), "r"(r[2]), "r"(r[3]));
}

// Exact path: total_vec256 % (256*UNROLL) == 0. Each thread: one 32B segment
// of a row per unrolled item (8 threads cover a 256B row).
__global__ __launch_bounds__(256)
void embed_gather_exact(const int* __restrict__ indices,
                        const uint32_t* __restrict__ weight,   // table as u32
                        float4* __restrict__ out)
{
    const long long stride     = (long long)gridDim.x * blockDim.x; // mult of 8
    const long long base       = (long long)blockIdx.x * blockDim.x + threadIdx.x;
    const int       seg        = (int)(base & 7);       // 32B segment in row
    const long long row0       = base >> 3;
    const long long row_stride = stride >> 3;

    // Batch 1: independent index loads
    int idx[UNROLL];
#pragma unroll
    for (int k = 0; k < UNROLL; k++)
        idx[k] = __ldg(indices + row0 + (long long)k * row_stride);

    // Batch 2: independent 256-bit gathers, table lines biased to stay in L2
    V8 v[UNROLL];
#pragma unroll
    for (int k = 0; k < UNROLL; k++)
        v[k] = ldg256_evict_last(weight + (long long)idx[k] * 64 + seg * 8);

    // Batch 3: streaming stores (2 x 128b per item)
#pragma unroll
    for (int k = 0; k < UNROLL; k++) {
        long long p = (base + (long long)k * stride) * 2;  // float4 index
        stcs128(out + p,     &v[k].r[0]);
        stcs128(out + p + 1, &v[k].r[4]);
    }
}

// General fallback: 128-bit, predicated, no cache hints.
__global__ __launch_bounds__(256)
void embed_gather_general(const int* __restrict__ indices,
                          const float4* __restrict__ weight,
                          float4* __restrict__ out,
                          long long total_vec)   // float4 count
{
    const long long stride = (long long)gridDim.x * blockDim.x;
    const long long base   = (long long)blockIdx.x * blockDim.x + threadIdx.x;

    int idx[UNROLL];
#pragma unroll
    for (int k = 0; k < UNROLL; k++) {
        long long p = base + (long long)k * stride;
        idx[k] = (p < total_vec) ? __ldg(indices + (p >> 4)) : 0;
    }
    float4 v[UNROLL];
#pragma unroll
    for (int k = 0; k < UNROLL; k++) {
        long long p = base + (long long)k * stride;
        if (p < total_vec)
            v[k] = __ldg(weight + (long long)idx[k] * 16 + (p & 15));
    }
#pragma unroll
    for (int k = 0; k < UNROLL; k++) {
        long long p = base + (long long)k * stride;
        if (p < total_vec) __stcs(out + p, v[k]);
    }
}

extern "C" void kernel_launch(void* const* d_in, const int* in_sizes, int n_in,
                              void* d_out, int out_size)
{
    const int* indices = (const int*)d_in[0];     // 819200 int32
    long long  num_rows = in_sizes[0];

    const int threads = 256;

    long long total_vec256 = num_rows * 8;        // 32B segments: 6,553,600
    long long per_block    = (long long)threads * UNROLL;  // 1024

    if (total_vec256 % per_block == 0) {
        int blocks = (int)(total_vec256 / per_block);      // 6400
        embed_gather_exact<<<blocks, threads>>>(
            indices, (const uint32_t*)d_in[1], (float4*)d_out);
    } else {
        long long total_vec = num_rows * 16;               // float4 count
        int blocks = (int)((total_vec + per_block - 1) / per_block);
        embed_gather_general<<<blocks, threads>>>(
            indices, (const float4*)d_in[1], (float4*)d_out, total_vec);
    }
}

// round 5
// speedup vs baseline: 1.2705x; 1.0393x over previous
#include <cuda_runtime.h>
#include <cstdint>

// Embedding gather: out[i, :] = weight[indices[i], :]
// 819200 rows x 64 fp32 = 256B/row.
// v5: LTS-cap model says ~423MB must cross L2 => floor ~63us. Tune the edges:
//   - 256-bit gathers with L2::evict_last (table stays), 8 threads/row
//   - 256-bit stores with L2::evict_first (pure streaming output)
//   - 512-thread blocks, UNROLL=4, exact division (3200 blocks), no predication

static constexpr int UNROLL = 4;

struct V8 { uint32_t r[8]; };

__device__ __forceinline__ V8 ldg256_evict_last(const uint32_t* p) {
    V8 v;
    asm volatile("ld.global.nc.L2::evict_last.v8.b32 {%0,%1,%2,%3,%4,%5,%6,%7}, [%8];"
                 : "=r"(v.r[0]), "=r"(v.r[1]), "=r"(v.r[2]), "=r"(v.r[3]),
                   "=r"(v.r[4]), "=r"(v.r[5]), "=r"(v.r[6]), "=r"(v.r[7])
                 : "l"(p));
    return v;
}

__device__ __forceinline__ void stg256_evict_first(uint32_t* p, const V8& v) {
    asm volatile("st.global.L2::evict_first.v8.b32 [%0], {%1,%2,%3,%4,%5,%6,%7,%8};"
                 :: "l"(p),
                    "r"(v.r[0]), "r"(v.r[1]), "r"(v.r[2]), "r"(v.r[3]),
                    "r"(v.r[4]), "r"(v.r[5]), "r"(v.r[6]), "r"(v.r[7]));
}

// Exact path: total 32B-segments divisible by blockDim*UNROLL.
__global__ __launch_bounds__(512)
void embed_gather_exact(const int* __restrict__ indices,
                        const uint32_t* __restrict__ weight,
                        uint32_t* __restrict__ out)
{
    const long long stride     = (long long)gridDim.x * blockDim.x; // mult of 8
    const long long base       = (long long)blockIdx.x * blockDim.x + threadIdx.x;
    const int       seg        = (int)(base & 7);      // 32B segment within row
    const long long row0       = base >> 3;
    const long long row_stride = stride >> 3;

    // Batch 1: independent index loads
    int idx[UNROLL];
#pragma unroll
    for (int k = 0; k < UNROLL; k++)
        idx[k] = __ldg(indices + row0 + (long long)k * row_stride);

    // Batch 2: independent 256-bit gathers; table lines biased to persist in L2
    V8 v[UNROLL];
#pragma unroll
    for (int k = 0; k < UNROLL; k++)
        v[k] = ldg256_evict_last(weight + (long long)idx[k] * 64 + seg * 8);

    // Batch 3: 256-bit streaming stores, evict-first (never re-read)
#pragma unroll
    for (int k = 0; k < UNROLL; k++)
        stg256_evict_first(out + (base + (long long)k * stride) * 8, v[k]);
}

// General fallback: 128-bit, predicated, no hints.
__global__ __launch_bounds__(512)
void embed_gather_general(const int* __restrict__ indices,
                          const float4* __restrict__ weight,
                          float4* __restrict__ out,
                          long long total_vec)   // float4 count
{
    const long long stride = (long long)gridDim.x * blockDim.x;
    const long long base   = (long long)blockIdx.x * blockDim.x + threadIdx.x;

    int idx[UNROLL];
#pragma unroll
    for (int k = 0; k < UNROLL; k++) {
        long long p = base + (long long)k * stride;
        idx[k] = (p < total_vec) ? __ldg(indices + (p >> 4)) : 0;
    }
    float4 v[UNROLL];
#pragma unroll
    for (int k = 0; k < UNROLL; k++) {
        long long p = base + (long long)k * stride;
        if (p < total_vec)
            v[k] = __ldg(weight + (long long)idx[k] * 16 + (p & 15));
    }
#pragma unroll
    for (int k = 0; k < UNROLL; k++) {
        long long p = base + (long long)k * stride;
        if (p < total_vec) __stcs(out + p, v[k]);
    }
}

extern "C" void kernel_launch(void* const* d_in, const int* in_sizes, int n_in,
                              void* d_out, int out_size)
{
    const int* indices  = (const int*)d_in[0];     // 819200 int32
    long long  num_rows = in_sizes[0];

    const int threads = 512;
    long long total_vec256 = num_rows * 8;                  // 6,553,600
    long long per_block    = (long long)threads * UNROLL;   // 2048

    if (total_vec256 % per_block == 0) {
        int blocks = (int)(total_vec256 / per_block);       // 3200
        embed_gather_exact<<<blocks, threads>>>(
            indices, (const uint32_t*)d_in[1], (uint32_t*)d_out);
    } else {
        long long total_vec = num_rows * 16;
        int blocks = (int)((total_vec + per_block - 1) / per_block);
        embed_gather_general<<<blocks, threads>>>(
            indices, (const float4*)d_in[1], (float4*)d_out, total_vec);
    }
}